// round 7
// baseline (speedup 1.0000x reference)
#include <cuda_runtime.h>
#include <math.h>
#include <stdint.h>

// Problem constants
#define H     200
#define G4    800          // 4*H
#define W     48
#define S     2047
#define MID   1023
#define BSENT 14           // sentences per block in word LSTM (148 blocks = 1/SM)
#define NCTX  147          // ceil(2047/14)
#define CH_T  1024         // steps per sentence-level chain (MID+1)

// sentence-level partitioning: one 16-CTA cluster per chain (8 CTAs per layer)
#define SPARTS 8           // partition CTAs per layer
#define CLSZ   16          // cluster size (nonportable)
#define SROWS  100         // gate rows per CTA (800/8)
#define SUNITS 25          // hidden units per CTA (200/8)
#define PADU   28          // padded units per part (float4 transport)
#define HLEN   224         // SPARTS*PADU padded h-vector length
#define PITCH  456         // floats per weight row (bank-conflict-free, 16B aligned)
#define HH_OFF 228         // offset of Whh half within a row (bank +4 vs x half)
#define NITER  56          // float4 GEMV iterations per segment (224/4)

// smem float offsets for sent kernel
#define OFF_XBUF 16        // [2][224] x double buffer (padded layout)
#define OFF_HBUF 464       // [2][224] own-layer h double buffer (padded layout)
#define OFF_GBUF 912       // [100]
#define OFF_BBUF 1012      // [100]
#define OFF_HOUT 1112      // [28]
#define OFF_WS   1140      // [100][PITCH]
#define SENT_SMEM_FLOATS (OFF_WS + SROWS * PITCH)

// ---------------- device scratch (no cudaMalloc allowed) ----------------
__device__ float g_WT[4][H * G4];          // [ctx_ih, ctx_hh, tgt_ih, tgt_hh] transposed [k][j]
__device__ float g_bias[2][G4];            // combined bih+bhh for ctx, tgt
__device__ float g_sent_emb[S * H];        // ctx embeddings
__device__ float g_tgt_emb[H];             // target-sentence embedding
__device__ float g_final[2 * H];           // [chain][H] top-layer final hidden

__device__ __forceinline__ float sigm(float x) { return 1.f / (1.f + expf(-x)); }

__device__ __forceinline__ uint32_t smem_u32(const void* p) {
    uint32_t a;
    asm("{ .reg .u64 t; cvta.to.shared.u64 t, %1; cvt.u32.u64 %0, t; }" : "=r"(a) : "l"(p));
    return a;
}
__device__ __forceinline__ uint32_t ctarank() {
    uint32_t r; asm("mov.u32 %0, %%cluster_ctarank;" : "=r"(r)); return r;
}
__device__ __forceinline__ void mbar_init(uint32_t a, uint32_t cnt) {
    asm volatile("mbarrier.init.shared.b64 [%0], %1;" :: "r"(a), "r"(cnt) : "memory");
}
// parity wait with cluster-scope acquire (orders peers' DSMEM stores before our reads)
__device__ __forceinline__ void mbar_wait(uint32_t a, uint32_t par) {
    uint32_t done;
    asm volatile("{\n\t.reg .pred p;\n\t"
                 "mbarrier.try_wait.parity.acquire.cluster.shared::cta.b64 p, [%1], %2;\n\t"
                 "selp.b32 %0, 1, 0, p;\n\t}" : "=r"(done) : "r"(a), "r"(par) : "memory");
    while (!done) {
        asm volatile("{\n\t.reg .pred p;\n\t"
                     "mbarrier.try_wait.parity.acquire.cluster.shared::cta.b64 p, [%1], %2, 0x989680;\n\t"
                     "selp.b32 %0, 1, 0, p;\n\t}" : "=r"(done) : "r"(a), "r"(par) : "memory");
    }
}
// push one float4 into rank's smem and arrive (release) on rank's mbarrier.
// arrive is by the SAME thread that stored -> release covers the store.
__device__ __forceinline__ void dsmem_store4_arrive(uint32_t laddr, float4 v,
                                                    uint32_t lmbar, uint32_t rank) {
    asm volatile("{\n\t.reg .b32 ra, rb;\n\t"
                 "mapa.shared::cluster.u32 ra, %0, %5;\n\t"
                 "st.shared::cluster.v4.f32 [ra], {%1, %2, %3, %4};\n\t"
                 "mapa.shared::cluster.u32 rb, %6, %5;\n\t"
                 "mbarrier.arrive.release.cluster.shared::cluster.b64 _, [rb];\n\t}"
                 :: "r"(laddr), "f"(v.x), "f"(v.y), "f"(v.z), "f"(v.w),
                    "r"(rank), "r"(lmbar) : "memory");
}
// remote arrive only (credit return)
__device__ __forceinline__ void dsmem_arrive(uint32_t lmbar, uint32_t rank) {
    asm volatile("{\n\t.reg .b32 rb;\n\t"
                 "mapa.shared::cluster.u32 rb, %0, %1;\n\t"
                 "mbarrier.arrive.release.cluster.shared::cluster.b64 _, [rb];\n\t}"
                 :: "r"(lmbar), "r"(rank) : "memory");
}
__device__ __forceinline__ void cluster_sync_() {
    asm volatile("barrier.cluster.arrive.aligned;" ::: "memory");
    asm volatile("barrier.cluster.wait.aligned;" ::: "memory");
}

// ---------------- kernel 1: transpose word-level weights + combine biases -------
__global__ void prep_kernel(const float* ci, const float* ch,
                            const float* ti, const float* th,
                            const float* cbi, const float* cbh,
                            const float* tbi, const float* tbh) {
    int idx = blockIdx.x * blockDim.x + threadIdx.x;
    if (idx < 4 * H * G4) {
        int m = idx / (H * G4);
        int r = idx % (H * G4);
        int k = r / G4;
        int j = r % G4;
        const float* src = (m == 0) ? ci : (m == 1) ? ch : (m == 2) ? ti : th;
        g_WT[m][r] = src[j * H + k];
    }
    if (idx < 2 * G4) {
        int m = idx / G4, j = idx % G4;
        g_bias[m][j] = m ? (tbi[j] + tbh[j]) : (cbi[j] + cbh[j]);
    }
}

// ---------------- kernel 2: word-level LSTMs (ctx batched + tgt) -----------------
// blocks 0..146: 14 ctx sentences each. block 147: target sentence (tgt weights).
__global__ __launch_bounds__(G4, 1) void word_lstm_kernel(const float* __restrict__ sents) {
    extern __shared__ float sm[];
    float* xs = sm;                      // [14][200]
    float* hs = xs + BSENT * H;          // [14][200]
    float* cs = hs + BSENT * H;          // [14][200]
    float* gt = cs + BSENT * H;          // [14][800]

    const int  bx     = blockIdx.x;
    const bool is_tgt = (bx == NCTX);
    const int  s0     = is_tgt ? MID : bx * BSENT;
    const int  nb     = is_tgt ? 1 : ((S - s0) < BSENT ? (S - s0) : BSENT);

    const float* __restrict__ WTih = is_tgt ? g_WT[2] : g_WT[0];
    const float* __restrict__ WThh = is_tgt ? g_WT[3] : g_WT[1];
    const float* __restrict__ bias = is_tgt ? g_bias[1] : g_bias[0];

    const int tid = threadIdx.x;          // == gate row j
    for (int i = tid; i < BSENT * H; i += G4) { xs[i] = 0.f; hs[i] = 0.f; cs[i] = 0.f; }
    const float bj = bias[tid];
    const float* wi = WTih + tid;
    const float* wh = WThh + tid;
    __syncthreads();

    for (int t = 0; t < W; t++) {
        for (int i = tid; i < nb * H; i += G4) {
            int b = i / H, k = i % H;
            xs[b * H + k] = sents[(long)(s0 + b) * (W * H) + t * H + k];
        }
        __syncthreads();

        float acc[BSENT];
        #pragma unroll
        for (int b = 0; b < BSENT; b++) acc[b] = bj;

        #pragma unroll 2
        for (int k = 0; k < H; k += 4) {
            float w0 = wi[(k + 0) * G4], w1 = wi[(k + 1) * G4];
            float w2 = wi[(k + 2) * G4], w3 = wi[(k + 3) * G4];
            #pragma unroll
            for (int b = 0; b < BSENT; b++) {
                float4 xv = *(const float4*)&xs[b * H + k];
                acc[b] += w0 * xv.x + w1 * xv.y + w2 * xv.z + w3 * xv.w;
            }
        }
        #pragma unroll 2
        for (int k = 0; k < H; k += 4) {
            float w0 = wh[(k + 0) * G4], w1 = wh[(k + 1) * G4];
            float w2 = wh[(k + 2) * G4], w3 = wh[(k + 3) * G4];
            #pragma unroll
            for (int b = 0; b < BSENT; b++) {
                float4 hv = *(const float4*)&hs[b * H + k];
                acc[b] += w0 * hv.x + w1 * hv.y + w2 * hv.z + w3 * hv.w;
            }
        }
        #pragma unroll
        for (int b = 0; b < BSENT; b++) gt[b * G4 + tid] = acc[b];
        __syncthreads();

        for (int i = tid; i < BSENT * H; i += G4) {
            int b = i / H, u = i % H;
            if (b < nb) {
                float ig = sigm(gt[b * G4 + u]);
                float fg = sigm(gt[b * G4 + H + u]);
                float gg = tanhf(gt[b * G4 + 2 * H + u]);
                float og = sigm(gt[b * G4 + 3 * H + u]);
                float c  = fg * cs[b * H + u] + ig * gg;
                cs[b * H + u] = c;
                hs[b * H + u] = og * tanhf(c);
            }
        }
        __syncthreads();
    }

    if (is_tgt) {
        for (int i = tid; i < H; i += G4) g_tgt_emb[i] = hs[i];
    } else {
        for (int i = tid; i < nb * H; i += G4) {
            int b = i / H, u = i % H;
            g_sent_emb[(s0 + b) * H + u] = hs[b * H + u];
        }
    }
}

// ---------------- kernel 3: sentence-level chains, 16-CTA cluster, all-DSMEM -----
// grid 32 = 2 clusters x 16 CTAs. chain = blockIdx.x/16.
// rank 0..7 = layer 0 parts, rank 8..15 = layer 1 parts. Each CTA: 25 units.
// Transport layout padded to 28 floats per part (7 float4 per destination),
// weight columns permuted to match; pad columns carry zero weights.
// Barrier counts: hbar/xbar 56 (8 CTAs x 7 lanes), cbar 8 (WAR credits).
__global__ __launch_bounds__(256, 1)
void sent_lstm_kernel(
    const float* __restrict__ pWih, const float* __restrict__ pWhh,
    const float* __restrict__ pbih, const float* __restrict__ pbhh,
    const float* __restrict__ qWih, const float* __restrict__ qWhh,
    const float* __restrict__ qbih, const float* __restrict__ qbhh) {

    extern __shared__ float sm[];
    float* xbuf = sm + OFF_XBUF;     // [2][224]
    float* hbuf = sm + OFF_HBUF;     // [2][224]
    float* gbuf = sm + OFF_GBUF;     // [100]
    float* bbuf = sm + OFF_BBUF;     // [100]
    float* hout = sm + OFF_HOUT;     // [28]
    float* ws   = sm + OFF_WS;       // [100][PITCH]

    const int tid   = threadIdx.x;   // 256 threads
    const int chain = blockIdx.x >> 4;
    const uint32_t rank = ctarank();
    const int layer = (int)(rank >> 3);
    const int part  = (int)(rank & 7);

    const float* Wih = chain ? qWih : pWih;
    const float* Whh = chain ? qWhh : pWhh;
    const float* bih = chain ? qbih : pbih;
    const float* bhh = chain ? qbhh : pbhh;

    const uint32_t smbase = smem_u32(sm);
    const uint32_t HBAR   = smbase;        // +b*8
    const uint32_t XBAR   = smbase + 16;   // +b*8
    const uint32_t CBAR   = smbase + 32;   // +b*8

    if (tid == 0) {
        mbar_init(HBAR,     SPARTS * 7);  mbar_init(HBAR + 8, SPARTS * 7);
        mbar_init(XBAR,     SPARTS * 7);  mbar_init(XBAR + 8, SPARTS * 7);
        mbar_init(CBAR,     SPARTS);      mbar_init(CBAR + 8, SPARTS);
    }
    for (int i = tid; i < 2 * HLEN; i += 256) { xbuf[i] = 0.f; hbuf[i] = 0.f; }
    if (tid < PADU) hout[tid] = 0.f;
    // weights: permuted padded layout. c<HLEN: x-half; HH_OFF<=c<HH_OFF+HLEN: h-half.
    for (int i = tid; i < SROWS * PITCH; i += 256) {
        int rr = i / PITCH, c = i % PITCH;
        int r  = (rr / SUNITS) * H + part * SUNITS + (rr % SUNITS);  // gate*200 + unit
        float v = 0.f;
        if (c < HLEN) {
            int p = c / PADU, u = c % PADU;
            if (u < SUNITS) v = Wih[layer * (G4 * H) + r * H + p * SUNITS + u];
        } else if (c >= HH_OFF && c < HH_OFF + HLEN) {
            int cc = c - HH_OFF;
            int p = cc / PADU, u = cc % PADU;
            if (u < SUNITS) v = Whh[layer * (G4 * H) + r * H + p * SUNITS + u];
        }
        ws[i] = v;
    }
    if (tid < SROWS) {
        int r = (tid / SUNITS) * H + part * SUNITS + (tid % SUNITS);
        bbuf[tid] = bih[layer * G4 + r] + bhh[layer * G4 + r];
    }
    __syncthreads();
    cluster_sync_();                 // all mbarriers + zeroed buffers visible cluster-wide

    float cstate = 0.f;              // cell state in registers of tid<25
    int ph_h0 = 0, ph_h1 = 0, ph_x0 = 0, ph_x1 = 0, ph_c0 = 0, ph_c1 = 0;

    const int r = tid >> 1, s = tid & 1;
    const float4* wv = (const float4*)(ws + r * PITCH + s * HH_OFF);

    for (int t = 0; t < CH_T; t++) {
        const int b = t & 1;
        if (layer == 0) {
            // WAR credit: layer1 consumed x(t-2) before we overwrite buffer b remotely
            if (t >= 2) {
                if (b == 0) { mbar_wait(CBAR, ph_c0); ph_c0 ^= 1; }
                else        { mbar_wait(CBAR + 8, ph_c1); ph_c1 ^= 1; }
            }
            if (tid < H) {   // scatter x into padded transport layout
                int sidx = chain ? (2 * MID - t) : t;
                float v = (sidx == MID) ? g_tgt_emb[tid] : g_sent_emb[sidx * H + tid];
                int p = tid / SUNITS, u = tid % SUNITS;
                xbuf[b * HLEN + p * PADU + u] = v;
            }
        } else {
            // x(t) pushed by layer0
            if (b == 0) { mbar_wait(XBAR, ph_x0); ph_x0 ^= 1; }
            else        { mbar_wait(XBAR + 8, ph_x1); ph_x1 ^= 1; }
        }
        // own-layer h(t-1)
        if (t > 0) {
            int hb = (t - 1) & 1;
            if (hb == 0) { mbar_wait(HBAR, ph_h0); ph_h0 ^= 1; }
            else         { mbar_wait(HBAR + 8, ph_h1); ph_h1 ^= 1; }
        }
        __syncthreads();

        // GEMV: 2 threads/row; s=0 -> Wih.x, s=1 -> Whh.h(t-1); uniform 56 float4 iters
        float ps = 0.f;
        if (tid < 2 * SROWS) {
            const float4* xv = (const float4*)(s ? (hbuf + ((t + 1) & 1) * HLEN)
                                                 : (xbuf + b * HLEN));
            float a0 = 0.f, a1 = 0.f, a2 = 0.f, a3 = 0.f;
            #pragma unroll 8
            for (int k = 0; k < NITER; k++) {
                float4 w = wv[k], x = xv[k];
                a0 += w.x * x.x; a1 += w.y * x.y;
                a2 += w.z * x.z; a3 += w.w * x.w;
            }
            ps = (a0 + a1) + (a2 + a3);
        }
        ps += __shfl_down_sync(0xffffffffu, ps, 1);
        if (tid < 2 * SROWS && s == 0) gbuf[r] = ps + bbuf[r];
        __syncthreads();

        // xbuf[b] fully consumed -> return credit to all layer0 CTAs (ranks 0..7)
        if (layer == 1 && tid < SPARTS) dsmem_arrive(CBAR + b * 8, (uint32_t)tid);

        // cell update (25 units); hout pads [25..27] stay zero
        if (tid < SUNITS) {
            float ig = sigm(gbuf[tid]);
            float fg = sigm(gbuf[SUNITS + tid]);
            float gg = tanhf(gbuf[2 * SUNITS + tid]);
            float og = sigm(gbuf[3 * SUNITS + tid]);
            float c  = fg * cstate + ig * gg;
            cstate = c;
            float h = og * tanhf(c);
            hout[tid] = h;
            if (layer == 1 && t == CH_T - 1)
                g_final[chain * H + part * SUNITS + tid] = h;
        }
        __syncthreads();

        // DSMEM pushes: warp w serves dest rank; lanes 0..6 carry 7 float4 (28 floats)
        {
            int lid = tid & 31, w = tid >> 5;   // 8 warps
            if (lid < 7) {
                float4 v = ((const float4*)hout)[lid];
                uint32_t slotH = (uint32_t)(OFF_HBUF + b * HLEN + part * PADU) * 4u + (uint32_t)lid * 16u;
                if (layer == 0) {
                    uint32_t slotX = (uint32_t)(OFF_XBUF + b * HLEN + part * PADU) * 4u + (uint32_t)lid * 16u;
                    dsmem_store4_arrive(smbase + slotH, v, HBAR + b * 8, (uint32_t)w);
                    dsmem_store4_arrive(smbase + slotX, v, XBAR + b * 8, (uint32_t)(w + 8));
                } else {
                    dsmem_store4_arrive(smbase + slotH, v, HBAR + b * 8, (uint32_t)(w + 8));
                }
            }
        }
    }

    // keep every CTA's smem alive until all cluster traffic has landed
    cluster_sync_();
}

// ---------------- kernel 4: final projection ------------------------------------
__global__ void fc_kernel(const float* __restrict__ fc_W, const float* __restrict__ fc_b,
                          float* __restrict__ out) {
    int j = threadIdx.x;
    if (j < H) {
        const float* ph = g_final;
        const float* qh = g_final + H;
        float acc = fc_b[j];
        const float* wr = fc_W + j * (2 * H);
        #pragma unroll 4
        for (int k = 0; k < H; k++) acc += ph[k] * wr[k];
        #pragma unroll 4
        for (int k = 0; k < H; k++) acc += qh[k] * wr[H + k];
        out[j] = acc;
    }
}

// ---------------- launcher ------------------------------------------------------
extern "C" void kernel_launch(void* const* d_in, const int* in_sizes, int n_in,
                              void* d_out, int out_size) {
    const float* sents    = (const float*)d_in[0];
    const float* ctx_Wih  = (const float*)d_in[1];
    const float* ctx_Whh  = (const float*)d_in[2];
    const float* ctx_bih  = (const float*)d_in[3];
    const float* ctx_bhh  = (const float*)d_in[4];
    const float* tgt_Wih  = (const float*)d_in[5];
    const float* tgt_Whh  = (const float*)d_in[6];
    const float* tgt_bih  = (const float*)d_in[7];
    const float* tgt_bhh  = (const float*)d_in[8];
    const float* prev_Wih = (const float*)d_in[9];
    const float* prev_Whh = (const float*)d_in[10];
    const float* prev_bih = (const float*)d_in[11];
    const float* prev_bhh = (const float*)d_in[12];
    const float* post_Wih = (const float*)d_in[13];
    const float* post_Whh = (const float*)d_in[14];
    const float* post_bih = (const float*)d_in[15];
    const float* post_bhh = (const float*)d_in[16];
    const float* fc_W     = (const float*)d_in[17];
    const float* fc_b     = (const float*)d_in[18];

    const size_t word_smem = (size_t)(3 * BSENT * H + BSENT * G4) * sizeof(float);  // 78400
    const size_t sent_smem = (size_t)SENT_SMEM_FLOATS * sizeof(float);              // 186960

    cudaFuncSetAttribute(word_lstm_kernel, cudaFuncAttributeMaxDynamicSharedMemorySize, (int)word_smem);
    cudaFuncSetAttribute(sent_lstm_kernel, cudaFuncAttributeMaxDynamicSharedMemorySize, (int)sent_smem);
    cudaFuncSetAttribute(sent_lstm_kernel, cudaFuncAttributeNonPortableClusterSizeAllowed, 1);

    prep_kernel<<<(4 * H * G4 + 255) / 256, 256>>>(ctx_Wih, ctx_Whh, tgt_Wih, tgt_Whh,
                                                   ctx_bih, ctx_bhh, tgt_bih, tgt_bhh);
    word_lstm_kernel<<<NCTX + 1, G4, word_smem>>>(sents);

    {
        cudaLaunchConfig_t cfg = {};
        cfg.gridDim  = dim3(2 * CLSZ, 1, 1);
        cfg.blockDim = dim3(256, 1, 1);
        cfg.dynamicSmemBytes = sent_smem;
        cfg.stream = 0;
        cudaLaunchAttribute attr[1];
        attr[0].id = cudaLaunchAttributeClusterDimension;
        attr[0].val.clusterDim.x = CLSZ;
        attr[0].val.clusterDim.y = 1;
        attr[0].val.clusterDim.z = 1;
        cfg.attrs = attr;
        cfg.numAttrs = 1;
        cudaLaunchKernelEx(&cfg, sent_lstm_kernel,
                           prev_Wih, prev_Whh, prev_bih, prev_bhh,
                           post_Wih, post_Whh, post_bih, post_bhh);
    }

    fc_kernel<<<1, 256>>>(fc_W, fc_b, (float*)d_out);
}

// round 9
// speedup vs baseline: 1.1553x; 1.1553x over previous
#include <cuda_runtime.h>
#include <math.h>
#include <stdint.h>

// Problem constants
#define H     200
#define G4    800          // 4*H
#define W     48
#define S     2047
#define MID   1023
#define BSENT 14           // sentences per block in word LSTM (148 blocks = 1/SM)
#define NCTX  147          // ceil(2047/14)
#define CH_T  1024         // steps per sentence-level chain (MID+1)
#define XTB   8            // t-steps per block in xg precompute

// sentence-level partitioning: one 16-CTA cluster per chain (8 CTAs per layer)
#define SPARTS 8           // partition CTAs per layer
#define CLSZ   16          // cluster size (nonportable)
#define SROWS  100         // gate rows per CTA (800/8)
#define SUNITS 25          // hidden units per CTA (200/8)
#define PITCH  424         // floats per weight row (R6 measured-good banking)
#define HH_OFF 204         // offset of Whh half within a row

// smem float offsets for sent kernel (R6 layout)
#define OFF_XBUF 16        // [2][200] x double buffer (layer-1 input)
#define OFF_HBUF 416       // [2][200] own-layer h double buffer
#define OFF_GBUF 816       // [100]
#define OFF_BBUF 916       // [100]
#define OFF_HOUT 1016      // [32]
#define OFF_WS   1048      // [100][PITCH]
#define SENT_SMEM_FLOATS (OFF_WS + SROWS * PITCH)

// ---------------- device scratch (no cudaMalloc allowed) ----------------
__device__ float g_WT[4][H * G4];          // word weights transposed [k][j]
__device__ float g_WTs[2][H * G4];         // sent layer-0 Wih transposed (prev, post)
__device__ float g_bias[2][G4];            // combined word biases (ctx, tgt)
__device__ float g_sent_emb[S * H];        // ctx embeddings
__device__ float g_tgt_emb[H];             // target-sentence embedding
__device__ float g_xg[2 * CH_T * G4];      // precomputed Wih0·x_t + bias0  [chain][t][800]
__device__ float g_final[2 * H];           // [chain][H] top-layer final hidden

__device__ __forceinline__ float sigm(float x) { return 1.f / (1.f + expf(-x)); }

__device__ __forceinline__ uint32_t smem_u32(const void* p) {
    uint32_t a;
    asm("{ .reg .u64 t; cvta.to.shared.u64 t, %1; cvt.u32.u64 %0, t; }" : "=r"(a) : "l"(p));
    return a;
}
__device__ __forceinline__ uint32_t ctarank() {
    uint32_t r; asm("mov.u32 %0, %%cluster_ctarank;" : "=r"(r)); return r;
}
__device__ __forceinline__ void mbar_init(uint32_t a, uint32_t cnt) {
    asm volatile("mbarrier.init.shared.b64 [%0], %1;" :: "r"(a), "r"(cnt) : "memory");
}
__device__ __forceinline__ void mbar_wait(uint32_t a, uint32_t par) {
    uint32_t done;
    asm volatile("{\n\t.reg .pred p;\n\t"
                 "mbarrier.try_wait.parity.acquire.cluster.shared::cta.b64 p, [%1], %2;\n\t"
                 "selp.b32 %0, 1, 0, p;\n\t}" : "=r"(done) : "r"(a), "r"(par) : "memory");
    while (!done) {
        asm volatile("{\n\t.reg .pred p;\n\t"
                     "mbarrier.try_wait.parity.acquire.cluster.shared::cta.b64 p, [%1], %2, 0x989680;\n\t"
                     "selp.b32 %0, 1, 0, p;\n\t}" : "=r"(done) : "r"(a), "r"(par) : "memory");
    }
}
// push one float into rank's smem and arrive (release) on rank's mbarrier.
__device__ __forceinline__ void dsmem_store_arrive(uint32_t laddr, float v, uint32_t lmbar, uint32_t rank) {
    asm volatile("{\n\t.reg .b32 ra, rb;\n\t"
                 "mapa.shared::cluster.u32 ra, %0, %2;\n\t"
                 "st.shared::cluster.f32 [ra], %1;\n\t"
                 "mapa.shared::cluster.u32 rb, %3, %2;\n\t"
                 "mbarrier.arrive.release.cluster.shared::cluster.b64 _, [rb];\n\t}"
                 :: "r"(laddr), "f"(v), "r"(rank), "r"(lmbar) : "memory");
}
__device__ __forceinline__ void dsmem_arrive(uint32_t lmbar, uint32_t rank) {
    asm volatile("{\n\t.reg .b32 rb;\n\t"
                 "mapa.shared::cluster.u32 rb, %0, %1;\n\t"
                 "mbarrier.arrive.release.cluster.shared::cluster.b64 _, [rb];\n\t}"
                 :: "r"(lmbar), "r"(rank) : "memory");
}
__device__ __forceinline__ void cluster_sync_() {
    asm volatile("barrier.cluster.arrive.aligned;" ::: "memory");
    asm volatile("barrier.cluster.wait.aligned;" ::: "memory");
}

// ---------------- kernel 1: transposes + combined biases -------------------------
__global__ void prep_kernel(const float* ci, const float* ch,
                            const float* ti, const float* th,
                            const float* cbi, const float* cbh,
                            const float* tbi, const float* tbh,
                            const float* pWih, const float* qWih) {
    int idx = blockIdx.x * blockDim.x + threadIdx.x;
    if (idx < 6 * H * G4) {
        int m = idx / (H * G4);
        int r = idx % (H * G4);
        int k = r / G4;
        int j = r % G4;
        const float* src = (m == 0) ? ci : (m == 1) ? ch : (m == 2) ? ti
                          : (m == 3) ? th : (m == 4) ? pWih : qWih;
        if (m < 4) g_WT[m][r] = src[j * H + k];
        else       g_WTs[m - 4][r] = src[j * H + k];   // layer-0 slice is first G4*H
    }
    if (idx < 2 * G4) {
        int m = idx / G4, j = idx % G4;
        g_bias[m][j] = m ? (tbi[j] + tbh[j]) : (cbi[j] + cbh[j]);
    }
}

// ---------------- kernel 2: word-level LSTMs (unchanged) -------------------------
__global__ __launch_bounds__(G4, 1) void word_lstm_kernel(const float* __restrict__ sents) {
    extern __shared__ float sm[];
    float* xs = sm;                      // [14][200]
    float* hs = xs + BSENT * H;          // [14][200]
    float* cs = hs + BSENT * H;          // [14][200]
    float* gt = cs + BSENT * H;          // [14][800]

    const int  bx     = blockIdx.x;
    const bool is_tgt = (bx == NCTX);
    const int  s0     = is_tgt ? MID : bx * BSENT;
    const int  nb     = is_tgt ? 1 : ((S - s0) < BSENT ? (S - s0) : BSENT);

    const float* __restrict__ WTih = is_tgt ? g_WT[2] : g_WT[0];
    const float* __restrict__ WThh = is_tgt ? g_WT[3] : g_WT[1];
    const float* __restrict__ bias = is_tgt ? g_bias[1] : g_bias[0];

    const int tid = threadIdx.x;          // == gate row j
    for (int i = tid; i < BSENT * H; i += G4) { xs[i] = 0.f; hs[i] = 0.f; cs[i] = 0.f; }
    const float bj = bias[tid];
    const float* wi = WTih + tid;
    const float* wh = WThh + tid;
    __syncthreads();

    for (int t = 0; t < W; t++) {
        for (int i = tid; i < nb * H; i += G4) {
            int b = i / H, k = i % H;
            xs[b * H + k] = sents[(long)(s0 + b) * (W * H) + t * H + k];
        }
        __syncthreads();

        float acc[BSENT];
        #pragma unroll
        for (int b = 0; b < BSENT; b++) acc[b] = bj;

        #pragma unroll 2
        for (int k = 0; k < H; k += 4) {
            float w0 = wi[(k + 0) * G4], w1 = wi[(k + 1) * G4];
            float w2 = wi[(k + 2) * G4], w3 = wi[(k + 3) * G4];
            #pragma unroll
            for (int b = 0; b < BSENT; b++) {
                float4 xv = *(const float4*)&xs[b * H + k];
                acc[b] += w0 * xv.x + w1 * xv.y + w2 * xv.z + w3 * xv.w;
            }
        }
        #pragma unroll 2
        for (int k = 0; k < H; k += 4) {
            float w0 = wh[(k + 0) * G4], w1 = wh[(k + 1) * G4];
            float w2 = wh[(k + 2) * G4], w3 = wh[(k + 3) * G4];
            #pragma unroll
            for (int b = 0; b < BSENT; b++) {
                float4 hv = *(const float4*)&hs[b * H + k];
                acc[b] += w0 * hv.x + w1 * hv.y + w2 * hv.z + w3 * hv.w;
            }
        }
        #pragma unroll
        for (int b = 0; b < BSENT; b++) gt[b * G4 + tid] = acc[b];
        __syncthreads();

        for (int i = tid; i < BSENT * H; i += G4) {
            int b = i / H, u = i % H;
            if (b < nb) {
                float ig = sigm(gt[b * G4 + u]);
                float fg = sigm(gt[b * G4 + H + u]);
                float gg = tanhf(gt[b * G4 + 2 * H + u]);
                float og = sigm(gt[b * G4 + 3 * H + u]);
                float c  = fg * cs[b * H + u] + ig * gg;
                cs[b * H + u] = c;
                hs[b * H + u] = og * tanhf(c);
            }
        }
        __syncthreads();
    }

    if (is_tgt) {
        for (int i = tid; i < H; i += G4) g_tgt_emb[i] = hs[i];
    } else {
        for (int i = tid; i < nb * H; i += G4) {
            int b = i / H, u = i % H;
            g_sent_emb[(s0 + b) * H + u] = hs[b * H + u];
        }
    }
}

// ---------------- kernel 2b: precompute layer-0 input gates ----------------------
__global__ __launch_bounds__(G4, 1) void xg_kernel(
    const float* __restrict__ pbih, const float* __restrict__ pbhh,
    const float* __restrict__ qbih, const float* __restrict__ qbhh) {
    __shared__ float xs[XTB * H];
    const int bx = blockIdx.x;
    const int chain = bx >> 7;              // 128 t-tiles per chain
    const int t0 = (bx & 127) * XTB;
    const int tid = threadIdx.x;            // 800, = gate row j

    for (int i = tid; i < XTB * H; i += G4) {
        int tt = i / H, k = i % H;
        int sidx = chain ? (2 * MID - (t0 + tt)) : (t0 + tt);
        xs[i] = (sidx == MID) ? g_tgt_emb[k] : g_sent_emb[sidx * H + k];
    }
    __syncthreads();

    const float* wt = (chain ? g_WTs[1] : g_WTs[0]) + tid;
    float bj = chain ? (qbih[tid] + qbhh[tid]) : (pbih[tid] + pbhh[tid]);
    float acc[XTB];
    #pragma unroll
    for (int tt = 0; tt < XTB; tt++) acc[tt] = bj;
    #pragma unroll 4
    for (int k = 0; k < H; k++) {
        float w = wt[k * G4];
        #pragma unroll
        for (int tt = 0; tt < XTB; tt++) acc[tt] += w * xs[tt * H + k];
    }
    #pragma unroll
    for (int tt = 0; tt < XTB; tt++)
        g_xg[(chain * CH_T + t0 + tt) * G4 + tid] = acc[tt];
}

// ---------------- kernel 3: sentence-level chains, 16-CTA cluster ----------------
__global__ __launch_bounds__(256, 1)
void sent_lstm_kernel(
    const float* __restrict__ pWih, const float* __restrict__ pWhh,
    const float* __restrict__ pbih, const float* __restrict__ pbhh,
    const float* __restrict__ qWih, const float* __restrict__ qWhh,
    const float* __restrict__ qbih, const float* __restrict__ qbhh) {

    extern __shared__ float sm[];
    float* xbuf = sm + OFF_XBUF;     // [2][200] (layer-1 input from layer-0)
    float* hbuf = sm + OFF_HBUF;     // [2][200]
    float* gbuf = sm + OFF_GBUF;     // [100]
    float* bbuf = sm + OFF_BBUF;     // [100] (layer-1 only)
    float* hout = sm + OFF_HOUT;     // [32]
    float* ws   = sm + OFF_WS;       // [100][PITCH]

    const int tid   = threadIdx.x;   // 256 threads
    const int chain = blockIdx.x >> 4;
    const uint32_t rank = ctarank();
    const int layer = (int)(rank >> 3);
    const int part  = (int)(rank & 7);

    const float* Wih = chain ? qWih : pWih;
    const float* Whh = chain ? qWhh : pWhh;
    const float* bih = chain ? qbih : pbih;
    const float* bhh = chain ? qbhh : pbhh;

    const uint32_t smbase = smem_u32(sm);
    const uint32_t HBAR   = smbase;        // +b*8
    const uint32_t XBAR   = smbase + 16;   // +b*8
    const uint32_t CBAR   = smbase + 32;   // +b*8

    if (tid == 0) {
        mbar_init(HBAR,     SPARTS * SUNITS);  mbar_init(HBAR + 8, SPARTS * SUNITS);
        mbar_init(XBAR,     SPARTS * SUNITS);  mbar_init(XBAR + 8, SPARTS * SUNITS);
        mbar_init(CBAR,     SPARTS);           mbar_init(CBAR + 8, SPARTS);
    }
    for (int i = tid; i < 2 * H; i += 256) { xbuf[i] = 0.f; hbuf[i] = 0.f; }
    for (int i = tid; i < SROWS * 2 * H; i += 256) {
        int rr = i / (2 * H), kk = i % (2 * H);
        int r  = (rr / SUNITS) * H + part * SUNITS + (rr % SUNITS);  // gate*200 + unit
        if (kk < H) ws[rr * PITCH + kk]              = Wih[layer * (G4 * H) + r * H + kk];
        else        ws[rr * PITCH + HH_OFF + kk - H] = Whh[layer * (G4 * H) + r * H + kk - H];
    }
    if (tid < SROWS) {
        int r = (tid / SUNITS) * H + part * SUNITS + (tid % SUNITS);
        bbuf[tid] = bih[layer * G4 + r] + bhh[layer * G4 + r];
    }
    __syncthreads();
    cluster_sync_();                 // mbarriers + zeroed buffers visible cluster-wide

    float cstate = 0.f;              // cell state in registers of tid<25
    int ph_h0 = 0, ph_h1 = 0, ph_x0 = 0, ph_x1 = 0, ph_c0 = 0, ph_c1 = 0;

    const int r = tid >> 1, s = tid & 1;
    const float4* wv1 = (const float4*)(ws + r * PITCH + s * HH_OFF);          // layer-1
    const float4* wv0 = (const float4*)(ws + r * PITCH + HH_OFF + s * 100);    // layer-0 (Whh split)
    const int grow = (r / SUNITS) * H + part * SUNITS + (r % SUNITS);
    const float* xgp = g_xg + (size_t)chain * CH_T * G4 + grow;

    for (int t = 0; t < CH_T; t++) {
        const int b = t & 1;
        const int hb2 = (t + 1) & 1;     // buffer holding h(t-1)

        // prefetch xg (register; no hazard) before any waits
        float xg = 0.f;
        if (layer == 0 && tid < 2 * SROWS && s == 0) xg = __ldcg(xgp + (size_t)t * G4);

        // waits
        if (layer == 1) {
            if (b == 0) { mbar_wait(XBAR, ph_x0); ph_x0 ^= 1; }
            else        { mbar_wait(XBAR + 8, ph_x1); ph_x1 ^= 1; }
        }
        if (t > 0) {
            int hb = (t - 1) & 1;
            if (hb == 0) { mbar_wait(HBAR, ph_h0); ph_h0 ^= 1; }
            else         { mbar_wait(HBAR + 8, ph_h1); ph_h1 ^= 1; }
        }
        __syncthreads();

        // GEMV
        float ps = 0.f;
        if (tid < 2 * SROWS) {
            if (layer == 0) {
                const float4* xv = (const float4*)(hbuf + hb2 * H + s * 100);
                float a0 = 0.f, a1 = 0.f, a2 = 0.f, a3 = 0.f;
                #pragma unroll
                for (int k = 0; k < 25; k++) {
                    float4 w = wv0[k], x = xv[k];
                    a0 += w.x * x.x; a1 += w.y * x.y;
                    a2 += w.z * x.z; a3 += w.w * x.w;
                }
                ps = (a0 + a1) + (a2 + a3);
            } else {
                const float4* xv = (const float4*)(s ? (hbuf + hb2 * H) : (xbuf + b * H));
                float a0 = 0.f, a1 = 0.f, a2 = 0.f, a3 = 0.f;
                #pragma unroll 10
                for (int k = 0; k < 50; k++) {
                    float4 w = wv1[k], x = xv[k];
                    a0 += w.x * x.x; a1 += w.y * x.y;
                    a2 += w.z * x.z; a3 += w.w * x.w;
                }
                ps = (a0 + a1) + (a2 + a3);
            }
        }
        ps += __shfl_down_sync(0xffffffffu, ps, 1);
        if (tid < 2 * SROWS && s == 0)
            gbuf[r] = ps + ((layer == 0) ? xg : bbuf[r]);
        __syncthreads();

        // layer-1 consumed xbuf[b] -> return credit to all layer-0 CTAs
        if (layer == 1 && tid < SPARTS) dsmem_arrive(CBAR + b * 8, (uint32_t)tid);

        // cell update (25 units)
        if (tid < SUNITS) {
            float ig = sigm(gbuf[tid]);
            float fg = sigm(gbuf[SUNITS + tid]);
            float gg = tanhf(gbuf[2 * SUNITS + tid]);
            float og = sigm(gbuf[3 * SUNITS + tid]);
            float c  = fg * cstate + ig * gg;
            cstate = c;
            float h = og * tanhf(c);
            hout[tid] = h;
            if (layer == 1 && t == CH_T - 1)
                g_final[chain * H + part * SUNITS + tid] = h;
        }
        __syncthreads();

        // layer-0: WAR credit before overwriting layer-1's xbuf[b] remotely
        if (layer == 0 && t >= 2) {
            if (b == 0) { mbar_wait(CBAR, ph_c0); ph_c0 ^= 1; }
            else        { mbar_wait(CBAR + 8, ph_c1); ph_c1 ^= 1; }
        }
        __syncthreads();

        // DSMEM pushes: warp w serves dest rank; lanes 0..24 carry the 25 values
        {
            int lid = tid & 31, w = tid >> 5;   // 8 warps
            if (lid < SUNITS) {
                float v = hout[lid];
                uint32_t slot = (uint32_t)(b * H + part * SUNITS + lid) * 4u;
                if (layer == 0) {
                    dsmem_store_arrive(smbase + OFF_HBUF * 4 + slot, v, HBAR + b * 8, (uint32_t)w);
                    dsmem_store_arrive(smbase + OFF_XBUF * 4 + slot, v, XBAR + b * 8, (uint32_t)(w + 8));
                } else {
                    dsmem_store_arrive(smbase + OFF_HBUF * 4 + slot, v, HBAR + b * 8, (uint32_t)(w + 8));
                }
            }
        }
    }

    cluster_sync_();   // keep smem alive until all cluster traffic lands
}

// ---------------- kernel 4: final projection (warp-per-output, coalesced) --------
__global__ void fc_kernel(const float* __restrict__ fc_W, const float* __restrict__ fc_b,
                          float* __restrict__ out) {
    __shared__ float feat[2 * H];
    const int tid = threadIdx.x;          // 256
    for (int i = tid; i < 2 * H; i += 256) feat[i] = g_final[i];   // FIXED: full 400 loaded
    __syncthreads();
    const int w = tid >> 5, lane = tid & 31;
    for (int j = w; j < H; j += 8) {
        const float* wr = fc_W + j * (2 * H);
        float acc = 0.f;
        for (int k = lane; k < 2 * H; k += 32) acc += feat[k] * wr[k];   // coalesced
        #pragma unroll
        for (int o = 16; o > 0; o >>= 1) acc += __shfl_down_sync(0xffffffffu, acc, o);
        if (lane == 0) out[j] = acc + fc_b[j];
    }
}

// ---------------- launcher ------------------------------------------------------
extern "C" void kernel_launch(void* const* d_in, const int* in_sizes, int n_in,
                              void* d_out, int out_size) {
    const float* sents    = (const float*)d_in[0];
    const float* ctx_Wih  = (const float*)d_in[1];
    const float* ctx_Whh  = (const float*)d_in[2];
    const float* ctx_bih  = (const float*)d_in[3];
    const float* ctx_bhh  = (const float*)d_in[4];
    const float* tgt_Wih  = (const float*)d_in[5];
    const float* tgt_Whh  = (const float*)d_in[6];
    const float* tgt_bih  = (const float*)d_in[7];
    const float* tgt_bhh  = (const float*)d_in[8];
    const float* prev_Wih = (const float*)d_in[9];
    const float* prev_Whh = (const float*)d_in[10];
    const float* prev_bih = (const float*)d_in[11];
    const float* prev_bhh = (const float*)d_in[12];
    const float* post_Wih = (const float*)d_in[13];
    const float* post_Whh = (const float*)d_in[14];
    const float* post_bih = (const float*)d_in[15];
    const float* post_bhh = (const float*)d_in[16];
    const float* fc_W     = (const float*)d_in[17];
    const float* fc_b     = (const float*)d_in[18];

    const size_t word_smem = (size_t)(3 * BSENT * H + BSENT * G4) * sizeof(float);  // 78400
    const size_t sent_smem = (size_t)SENT_SMEM_FLOATS * sizeof(float);              // 173792

    cudaFuncSetAttribute(word_lstm_kernel, cudaFuncAttributeMaxDynamicSharedMemorySize, (int)word_smem);
    cudaFuncSetAttribute(sent_lstm_kernel, cudaFuncAttributeMaxDynamicSharedMemorySize, (int)sent_smem);
    cudaFuncSetAttribute(sent_lstm_kernel, cudaFuncAttributeNonPortableClusterSizeAllowed, 1);

    prep_kernel<<<(6 * H * G4 + 255) / 256, 256>>>(ctx_Wih, ctx_Whh, tgt_Wih, tgt_Whh,
                                                   ctx_bih, ctx_bhh, tgt_bih, tgt_bhh,
                                                   prev_Wih, post_Wih);
    word_lstm_kernel<<<NCTX + 1, G4, word_smem>>>(sents);
    xg_kernel<<<256, G4>>>(prev_bih, prev_bhh, post_bih, post_bhh);

    {
        cudaLaunchConfig_t cfg = {};
        cfg.gridDim  = dim3(2 * CLSZ, 1, 1);
        cfg.blockDim = dim3(256, 1, 1);
        cfg.dynamicSmemBytes = sent_smem;
        cfg.stream = 0;
        cudaLaunchAttribute attr[1];
        attr[0].id = cudaLaunchAttributeClusterDimension;
        attr[0].val.clusterDim.x = CLSZ;
        attr[0].val.clusterDim.y = 1;
        attr[0].val.clusterDim.z = 1;
        cfg.attrs = attr;
        cfg.numAttrs = 1;
        cudaLaunchKernelEx(&cfg, sent_lstm_kernel,
                           prev_Wih, prev_Whh, prev_bih, prev_bhh,
                           post_Wih, post_Whh, post_bih, post_bhh);
    }

    fc_kernel<<<1, 256>>>(fc_W, fc_b, (float*)d_out);
}